// round 2
// baseline (speedup 1.0000x reference)
#include <cuda_runtime.h>
#include <cuda_bf16.h>

// NeuralTexture: grid_sample bilinear (align_corners=True, border padding)
// tex: clip(data, LO, HI), data [C=16, T=1024, T=1024]
// grid: x [B=4, H=768, W=768, 2] in [-1,1]
// out:  [B, C, H, W] fp32
//
// Strategy: transpose texture to channel-last [T, T, C] into a __device__
// scratch (clamp fused). Each tap then reads 16 contiguous floats (4x float4),
// cutting L2 sector traffic ~4x vs the channel-major layout. Texture (64MB)
// is fully L2-resident, so the main kernel is L2-gather-throughput bound.

#define C_CH 16
#define TEXD 1024
#define BB   4
#define HH   768
#define WW   768
#define CLAMP_LO (-123.68f)
#define CLAMP_HI (151.061f)

// 1024*1024 texels * 16 channels * 4B = 64 MB, stored as float4 for alignment.
__device__ float4 g_tex_cl[TEXD * TEXD * (C_CH / 4)];

// --- Kernel 1: clamp + transpose [C,T,T] -> [T*T, C] (channel-last) ---
__global__ __launch_bounds__(256) void prep_kernel(const float* __restrict__ data) {
    const int t = blockIdx.x * blockDim.x + threadIdx.x;  // texel 0..TEXD*TEXD-1
    if (t >= TEXD * TEXD) return;

    float v[C_CH];
#pragma unroll
    for (int c = 0; c < C_CH; c++) {
        // consecutive threads -> consecutive addresses per channel: coalesced
        float x = __ldg(data + (size_t)c * (TEXD * TEXD) + t);
        v[c] = fminf(fmaxf(x, CLAMP_LO), CLAMP_HI);
    }
    float4* dst = g_tex_cl + (size_t)t * (C_CH / 4);
#pragma unroll
    for (int k = 0; k < C_CH / 4; k++) {
        // warp writes contiguous 2KB region: sector-coalesced
        dst[k] = make_float4(v[4 * k + 0], v[4 * k + 1], v[4 * k + 2], v[4 * k + 3]);
    }
}

// --- Kernel 2: bilinear gather, one thread per output pixel (b,h,w) ---
__global__ __launch_bounds__(256, 8) void sample_kernel(const float* __restrict__ grid,
                                                        float* __restrict__ out) {
    const int idx = blockIdx.x * blockDim.x + threadIdx.x;
    const int NPIX = BB * HH * WW;
    if (idx >= NPIX) return;

    // grid is [B,H,W,2] contiguous: float2 per pixel, coalesced
    const float2 g = __ldg(((const float2*)grid) + idx);

    // align_corners=True mapping, then clamp to [0, T-1]
    float ix = (g.x + 1.0f) * 0.5f * (float)(TEXD - 1);
    float iy = (g.y + 1.0f) * 0.5f * (float)(TEXD - 1);
    ix = fminf(fmaxf(ix, 0.0f), (float)(TEXD - 1));
    iy = fminf(fmaxf(iy, 0.0f), (float)(TEXD - 1));

    const float x0f = floorf(ix);
    const float y0f = floorf(iy);
    const float wx = ix - x0f;
    const float wy = iy - y0f;

    // ix,iy clamped to [0, T-1] already => x0,y0 in [0, T-1]
    const int x0 = (int)x0f;
    const int y0 = (int)y0f;
    const int x1 = min(x0 + 1, TEXD - 1);
    const int y1 = min(y0 + 1, TEXD - 1);

    const float w00 = (1.0f - wx) * (1.0f - wy);
    const float w01 = wx * (1.0f - wy);
    const float w10 = (1.0f - wx) * wy;
    const float w11 = wx * wy;

    const float4* __restrict__ p00 = g_tex_cl + ((size_t)y0 * TEXD + x0) * (C_CH / 4);
    const float4* __restrict__ p01 = g_tex_cl + ((size_t)y0 * TEXD + x1) * (C_CH / 4);
    const float4* __restrict__ p10 = g_tex_cl + ((size_t)y1 * TEXD + x0) * (C_CH / 4);
    const float4* __restrict__ p11 = g_tex_cl + ((size_t)y1 * TEXD + x1) * (C_CH / 4);

    // Batch ALL 16 LDG.128 up front: max MLP to hide L2-hit latency.
    float4 a0 = p00[0], a1 = p00[1], a2 = p00[2], a3 = p00[3];
    float4 b0 = p01[0], b1 = p01[1], b2 = p01[2], b3 = p01[3];
    float4 c0 = p10[0], c1 = p10[1], c2 = p10[2], c3 = p10[3];
    float4 d0 = p11[0], d1 = p11[1], d2 = p11[2], d3 = p11[3];

    // out[b, c, h, w]: base = b*C*H*W + h*W + w; channel stride = H*W
    const int w_ = idx % WW;
    const int h_ = (idx / WW) % HH;
    const int b_ = idx / (WW * HH);
    const size_t HW = (size_t)HH * WW;
    float* __restrict__ obase = out + (size_t)b_ * C_CH * HW + (size_t)h_ * WW + w_;

    float4 av[4] = {a0, a1, a2, a3};
    float4 bv[4] = {b0, b1, b2, b3};
    float4 cv[4] = {c0, c1, c2, c3};
    float4 dv[4] = {d0, d1, d2, d3};

#pragma unroll
    for (int k = 0; k < 4; k++) {
        const float4 a = av[k], b4 = bv[k], c4 = cv[k], d = dv[k];
        float r0 = a.x * w00 + b4.x * w01 + c4.x * w10 + d.x * w11;
        float r1 = a.y * w00 + b4.y * w01 + c4.y * w10 + d.y * w11;
        float r2 = a.z * w00 + b4.z * w01 + c4.z * w10 + d.z * w11;
        float r3 = a.w * w00 + b4.w * w01 + c4.w * w10 + d.w * w11;

        // per-channel stores: consecutive threads -> consecutive w_ => coalesced 128B
        obase[(size_t)(4 * k + 0) * HW] = r0;
        obase[(size_t)(4 * k + 1) * HW] = r1;
        obase[(size_t)(4 * k + 2) * HW] = r2;
        obase[(size_t)(4 * k + 3) * HW] = r3;
    }
}

extern "C" void kernel_launch(void* const* d_in, const int* in_sizes, int n_in,
                              void* d_out, int out_size) {
    const float* x = (const float*)d_in[0];     // [B,H,W,2]
    const float* data = (const float*)d_in[1];  // [C,T,T]
    float* out = (float*)d_out;                 // [B,C,H,W]

    {
        const int n = TEXD * TEXD;
        prep_kernel<<<(n + 255) / 256, 256>>>(data);
    }
    {
        const int n = BB * HH * WW;
        sample_kernel<<<(n + 255) / 256, 256>>>(x, out);
    }
}

// round 13
// speedup vs baseline: 1.4938x; 1.4938x over previous
#include <cuda_runtime.h>
#include <cuda_bf16.h>

// NeuralTexture: grid_sample bilinear (align_corners=True, border padding)
// tex = clip(data, LO, HI), data [C=16, T=1024, T=1024]
// grid: x [B=4, H=768, W=768, 2] in [-1,1]; out [B, C, H, W] fp32
//
// R2 profile: sample kernel L1-wavefront bound (L1=82.8%, L2=59.2%).
// This round: 4 lanes cooperate per pixel (lane k loads channel-chunk k of
// each tap) so one LDG instruction touches ~8 lines instead of ~32, cutting
// L1 gather wavefronts ~4x. Results staged through smem for coalesced stores.
// Output uses __stcs (evict-first) to keep the 64MB texture L2-resident.

#define C_CH 16
#define TEXD 1024
#define BB   4
#define HH   768
#define WW   768
#define CLAMP_LO (-123.68f)
#define CLAMP_HI (151.061f)
#define PIX_PER_BLK 64
#define SROW 17  // padded smem row (floats) -> conflict-free LDS on read side

// 1024*1024 texels * 16 channels * 4B = 64 MB, channel-last, float4-aligned.
__device__ float4 g_tex_cl[TEXD * TEXD * (C_CH / 4)];

// --- Kernel 1: clamp + transpose [C,T,T] -> [T*T, C] (channel-last) ---
__global__ __launch_bounds__(256) void prep_kernel(const float* __restrict__ data) {
    const int t = blockIdx.x * blockDim.x + threadIdx.x;  // texel 0..TEXD*TEXD-1
    if (t >= TEXD * TEXD) return;

    float v[C_CH];
#pragma unroll
    for (int c = 0; c < C_CH; c++) {
        float x = __ldg(data + (size_t)c * (TEXD * TEXD) + t);
        v[c] = fminf(fmaxf(x, CLAMP_LO), CLAMP_HI);
    }
    float4* dst = g_tex_cl + (size_t)t * (C_CH / 4);
#pragma unroll
    for (int k = 0; k < C_CH / 4; k++) {
        dst[k] = make_float4(v[4 * k + 0], v[4 * k + 1], v[4 * k + 2], v[4 * k + 3]);
    }
}

// --- Kernel 2: cooperative bilinear gather: 4 lanes per pixel ---
__global__ __launch_bounds__(256) void sample_kernel(const float* __restrict__ grid,
                                                     float* __restrict__ out) {
    __shared__ float s_res[PIX_PER_BLK * SROW];

    const int tid = threadIdx.x;
    const int pxl = tid >> 2;   // 0..63 local pixel
    const int k   = tid & 3;    // channel chunk 0..3 (channels 4k..4k+3)
    const int px  = blockIdx.x * PIX_PER_BLK + pxl;  // global pixel

    // 4 lanes of a pixel load the same float2 -> L1 broadcast, 1 line per LDG
    const float2 g = __ldg(((const float2*)grid) + px);

    // align_corners=True mapping, clamp to [0, T-1]
    float ix = (g.x + 1.0f) * 0.5f * (float)(TEXD - 1);
    float iy = (g.y + 1.0f) * 0.5f * (float)(TEXD - 1);
    ix = fminf(fmaxf(ix, 0.0f), (float)(TEXD - 1));
    iy = fminf(fmaxf(iy, 0.0f), (float)(TEXD - 1));

    const float x0f = floorf(ix);
    const float y0f = floorf(iy);
    const float wx = ix - x0f;
    const float wy = iy - y0f;

    const int x0 = (int)x0f;
    const int y0 = (int)y0f;
    const int x1 = min(x0 + 1, TEXD - 1);
    const int y1 = min(y0 + 1, TEXD - 1);

    const float w00 = (1.0f - wx) * (1.0f - wy);
    const float w01 = wx * (1.0f - wy);
    const float w10 = (1.0f - wx) * wy;
    const float w11 = wx * wy;

    // Each lane loads only its 16B chunk of each 64B texel.
    // Within one LDG instruction, the 4 lanes of a pixel hit the same 128B line.
    const float4 a = __ldg(g_tex_cl + ((size_t)y0 * TEXD + x0) * 4 + k);
    const float4 b = __ldg(g_tex_cl + ((size_t)y0 * TEXD + x1) * 4 + k);
    const float4 c = __ldg(g_tex_cl + ((size_t)y1 * TEXD + x0) * 4 + k);
    const float4 d = __ldg(g_tex_cl + ((size_t)y1 * TEXD + x1) * 4 + k);

    // Output base: compute before the barrier so address math overlaps it.
    const int base_px = blockIdx.x * PIX_PER_BLK;
    const int w0 = base_px % WW;                 // WW % 64 == 0 -> block shares (b,h)
    const int h_ = (base_px / WW) % HH;
    const int b_ = base_px / (WW * HH);
    const size_t HW = (size_t)HH * WW;
    float* __restrict__ obase = out + (size_t)b_ * C_CH * HW + (size_t)h_ * WW + w0;

    const float r0 = a.x * w00 + b.x * w01 + c.x * w10 + d.x * w11;
    const float r1 = a.y * w00 + b.y * w01 + c.y * w10 + d.y * w11;
    const float r2 = a.z * w00 + b.z * w01 + c.z * w10 + d.z * w11;
    const float r3 = a.w * w00 + b.w * w01 + c.w * w10 + d.w * w11;

    // Stage into smem: [pixel][channel], row padded to 17 floats
    float* srow = s_res + pxl * SROW + 4 * k;
    srow[0] = r0;
    srow[1] = r1;
    srow[2] = r2;
    srow[3] = r3;
    __syncthreads();

    // Coalesced output: 64 px * 16 ch = 1024 floats, 4 per thread.
#pragma unroll
    for (int j = 0; j < 4; j++) {
        const int e = tid + j * 256;
        const int ch = e >> 6;        // 0..15
        const int p  = e & 63;        // 0..63, consecutive within a warp
        // stride-17 LDS: conflict-free; STG 128B coalesced; evict-first to
        // keep texture resident in L2.
        __stcs(obase + (size_t)ch * HW + p, s_res[p * SROW + ch]);
    }
}

extern "C" void kernel_launch(void* const* d_in, const int* in_sizes, int n_in,
                              void* d_out, int out_size) {
    const float* x = (const float*)d_in[0];     // [B,H,W,2]
    const float* data = (const float*)d_in[1];  // [C,T,T]
    float* out = (float*)d_out;                 // [B,C,H,W]

    {
        const int n = TEXD * TEXD;
        prep_kernel<<<(n + 255) / 256, 256>>>(data);
    }
    {
        const int npix = BB * HH * WW;             // 2,359,296 (divisible by 64)
        const int nblk = npix / PIX_PER_BLK;       // 36,864
        sample_kernel<<<nblk, 256>>>(x, out);
    }
}